// round 14
// baseline (speedup 1.0000x reference)
#include <cuda_runtime.h>
#include <math.h>

#define B_SZ 1024
#define C_SZ 256
#define DF   512
#define DT   512
#define NHID 32
#define KSPLIT 2

// Scratch (allocation-free: __device__ globals)
__device__ float g_QkP[KSPLIT][B_SZ * DF];   // split-K partials of Q @ Wk_w
__device__ float g_accP[2][B_SZ * DF];       // per-half UNNORMALIZED weighted feature sums
__device__ float g_lp[2][B_SZ];              // per-half sum of exp weights
__device__ float g_abs[2][B_SZ];             // per-half sum of |f|
__device__ float g_gate[B_SZ];               // sigmoid gate per b
__device__ float g_outP[KSPLIT][B_SZ * DT];  // split-K partials of acc_total @ Wv^T

// ---------------------------------------------------------------------------
// helpers
// ---------------------------------------------------------------------------
__device__ __forceinline__ void cp_async16(float* dst, const float* src) {
    unsigned s = (unsigned)__cvta_generic_to_shared(dst);
    asm volatile("cp.async.cg.shared.global [%0], [%1], 16;\n" :: "r"(s), "l"(src) : "memory");
}
__device__ __forceinline__ unsigned long long pack2(float x) {
    unsigned long long r;
    asm("mov.b64 %0, {%1, %1};" : "=l"(r) : "r"(__float_as_uint(x)));
    return r;
}
__device__ __forceinline__ void ffma2(unsigned long long& acc, unsigned long long a,
                                      unsigned long long w) {
    asm("fma.rn.f32x2 %0, %1, %2, %0;" : "+l"(acc) : "l"(a), "l"(w));
}
__device__ __forceinline__ float lo32(unsigned long long v) {
    return __uint_as_float((unsigned)v);
}
__device__ __forceinline__ float hi32(unsigned long long v) {
    return __uint_as_float((unsigned)(v >> 32));
}

// ---------------------------------------------------------------------------
// Kernel 1: split-K partial of Qk[b][f] = sum_t Q[b][t] * Wk[t][f]
// Tile 32b x 128f, K-half 256 (8 iters of 32), 256 threads, 4x4 f32x2/thread.
// grid (4, 32, 2) = 256 CTAs -> 2/SM co-resident.
// ---------------------------------------------------------------------------
__global__ __launch_bounds__(256) void qk_gemm(const float* __restrict__ Q,
                                               const float* __restrict__ Wk) {
    __shared__ float As[2][32 * 36];   // [k][b], stride 36
    __shared__ float Bs[2][32 * 128];  // [k][f]
    const int tid  = threadIdx.x;
    const int b0   = blockIdx.y * 32;
    const int f0   = blockIdx.x * 128;
    const int kz   = blockIdx.z * (DT / KSPLIT);
    const int wq   = tid >> 5;
    const int lane = tid & 31;
    const int brow = tid >> 3;
    const int kc   = (tid & 7) * 4;
    const int kr   = tid >> 5;

    unsigned long long acc[4][2] = {};

    float4 rA = *(const float4*)(Q + (size_t)(b0 + brow) * DT + kz + kc);
    #pragma unroll
    for (int p = 0; p < 4; p++) {
        int kk = kr + p * 8;
        cp_async16(&Bs[0][kk * 128 + lane * 4], Wk + (size_t)(kz + kk) * DF + f0 + lane * 4);
    }
    asm volatile("cp.async.commit_group;\n" ::: "memory");

    #pragma unroll 1
    for (int it = 0; it < 8; it++) {
        const int cur = it & 1, nxt = cur ^ 1;
        As[cur][(kc + 0) * 36 + brow] = rA.x;
        As[cur][(kc + 1) * 36 + brow] = rA.y;
        As[cur][(kc + 2) * 36 + brow] = rA.z;
        As[cur][(kc + 3) * 36 + brow] = rA.w;
        if (it < 7) {
            const int k0n = kz + (it + 1) * 32;
            rA = *(const float4*)(Q + (size_t)(b0 + brow) * DT + k0n + kc);
            #pragma unroll
            for (int p = 0; p < 4; p++) {
                int kk = kr + p * 8;
                cp_async16(&Bs[nxt][kk * 128 + lane * 4],
                           Wk + (size_t)(k0n + kk) * DF + f0 + lane * 4);
            }
            asm volatile("cp.async.commit_group;\n" ::: "memory");
            asm volatile("cp.async.wait_group 1;\n" ::: "memory");
        } else {
            asm volatile("cp.async.wait_group 0;\n" ::: "memory");
        }
        __syncthreads();
        #pragma unroll
        for (int kk = 0; kk < 32; kk++) {
            float4 a4 = *(const float4*)(&As[cur][kk * 36 + wq * 4]);
            ulonglong2 w = *(const ulonglong2*)(&Bs[cur][kk * 128 + lane * 4]);
            unsigned long long a0 = pack2(a4.x), a1 = pack2(a4.y),
                               a2 = pack2(a4.z), a3 = pack2(a4.w);
            ffma2(acc[0][0], a0, w.x); ffma2(acc[0][1], a0, w.y);
            ffma2(acc[1][0], a1, w.x); ffma2(acc[1][1], a1, w.y);
            ffma2(acc[2][0], a2, w.x); ffma2(acc[2][1], a2, w.y);
            ffma2(acc[3][0], a3, w.x); ffma2(acc[3][1], a3, w.y);
        }
        __syncthreads();
    }
    float* dst = g_QkP[blockIdx.z];
    #pragma unroll
    for (int i = 0; i < 4; i++) {
        float4 v = make_float4(lo32(acc[i][0]), hi32(acc[i][0]),
                               lo32(acc[i][1]), hi32(acc[i][1]));
        *(float4*)(dst + (size_t)(b0 + wq * 4 + i) * DF + f0 + lane * 4) = v;
    }
}

// ---------------------------------------------------------------------------
// Kernel 2: half-batch attention. blockIdx.x = b, blockIdx.y = half (128 ch).
// grid 2048 -> ~7 waves at 2 CTAs/SM -> tiny tail.
// Register single-read: warp w owns channel w of each 16-ch chunk; Qk held in
// registers across chunks. One barrier per chunk. exp without max shift
// (scores tiny; shift cancels exactly in normalization).
// Writes UNNORMALIZED partial acc + partial (l, sum|f|).
// ---------------------------------------------------------------------------
__global__ __launch_bounds__(512, 2) void attn_kernel(const float* __restrict__ feat) {
    extern __shared__ float sm[];
    float* Qks = sm;                  // 512 (Qk row, scaled)
    float* buf = sm + 512;            // 3 * 16 * 512 ring (reused for reduction)
    float* aux = buf + 3 * 16 * DF;   // 32: l parts / abs parts

    const int b    = blockIdx.x;
    const int half = blockIdx.y;
    const int tid  = threadIdx.x;
    const int lane = tid & 31;
    const int wid  = tid >> 5;
    const float* Fb = feat + (size_t)b * C_SZ * DF + (size_t)half * 128 * DF;

    const float inv_sqrt_d = 0.044194173824159216f; // 1/sqrt(512)
    Qks[tid] = (g_QkP[0][(size_t)b * DF + tid] + g_QkP[1][(size_t)b * DF + tid]) * inv_sqrt_d;

    // prologue: chunks 0 and 1 in flight (16 ch x 512 f = 2048 f4, 4/thread)
    #pragma unroll
    for (int s = 0; s < 2; s++) {
        float* dst = buf + s * 16 * DF;
        const float* src = Fb + (size_t)s * 16 * DF;
        #pragma unroll
        for (int i = 0; i < 4; i++)
            cp_async16(dst + 4 * (tid + i * 512), src + 4 * (tid + i * 512));
        asm volatile("cp.async.commit_group;\n" ::: "memory");
    }
    __syncthreads();

    // hoist Qk into registers for the whole loop
    const float4* Qk4 = (const float4*)Qks;
    float4 q[4];
    #pragma unroll
    for (int k = 0; k < 4; k++) q[k] = Qk4[lane + 32 * k];

    float4 acc[4];
    #pragma unroll
    for (int k = 0; k < 4; k++) acc[k] = make_float4(0.f, 0.f, 0.f, 0.f);
    float lpart = 0.f;
    float wabs  = 0.f;

    #pragma unroll 1
    for (int ch = 0; ch < 8; ch++) {
        if (ch < 7) asm volatile("cp.async.wait_group 1;\n" ::: "memory");
        else        asm volatile("cp.async.wait_group 0;\n" ::: "memory");
        __syncthreads();   // sole barrier: chunk ch resident; all warps past ch-1

        if (ch + 2 < 8) {
            float* dst = buf + ((ch + 2) % 3) * 16 * DF;
            const float* src = Fb + (size_t)(ch + 2) * 16 * DF;
            #pragma unroll
            for (int i = 0; i < 4; i++)
                cp_async16(dst + 4 * (tid + i * 512), src + 4 * (tid + i * 512));
            asm volatile("cp.async.commit_group;\n" ::: "memory");
        }

        const float4* row4 = (const float4*)(buf + (ch % 3) * 16 * DF + wid * DF);
        float4 v[4];
        float s = 0.f, a = 0.f;
        #pragma unroll
        for (int k = 0; k < 4; k++) {
            v[k] = row4[lane + 32 * k];
            s = fmaf(q[k].x, v[k].x, s); s = fmaf(q[k].y, v[k].y, s);
            s = fmaf(q[k].z, v[k].z, s); s = fmaf(q[k].w, v[k].w, s);
            a += fabsf(v[k].x) + fabsf(v[k].y) + fabsf(v[k].z) + fabsf(v[k].w);
        }
        #pragma unroll
        for (int o = 16; o; o >>= 1) {
            s += __shfl_xor_sync(0xffffffffu, s, o);
            a += __shfl_xor_sync(0xffffffffu, a, o);
        }
        float p = __expf(s);
        lpart += p;
        wabs  += a;
        #pragma unroll
        for (int k = 0; k < 4; k++) {
            acc[k].x = fmaf(p, v[k].x, acc[k].x);
            acc[k].y = fmaf(p, v[k].y, acc[k].y);
            acc[k].z = fmaf(p, v[k].z, acc[k].z);
            acc[k].w = fmaf(p, v[k].w, acc[k].w);
        }
    }

    // cross-warp reduction of partial accumulators
    __syncthreads();
    float4* red = (float4*)buf;            // [16 warps][128 f4]
    #pragma unroll
    for (int k = 0; k < 4; k++) red[wid * 128 + lane + 32 * k] = acc[k];
    if (lane == 0) { aux[wid] = lpart; aux[16 + wid] = wabs; }
    __syncthreads();

    if (tid < 128) {
        float4 s4 = make_float4(0.f, 0.f, 0.f, 0.f);
        #pragma unroll
        for (int w = 0; w < 16; w++) {
            float4 v = red[w * 128 + tid];
            s4.x += v.x; s4.y += v.y; s4.z += v.z; s4.w += v.w;
        }
        *(float4*)(g_accP[half] + (size_t)b * DF + tid * 4) = s4;
    }
    if (tid == 0) {
        float l = 0.f, t = 0.f;
        #pragma unroll
        for (int w = 0; w < 16; w++) { l += aux[w]; t += aux[16 + w]; }
        g_lp[half][b]  = l;
        g_abs[half][b] = t;
    }
}

// ---------------------------------------------------------------------------
// Kernel 2b: gate MLP. One CTA (128 threads) per b. g1w is L2-hot.
// ---------------------------------------------------------------------------
__global__ __launch_bounds__(128) void gate_kernel(const float* __restrict__ Q,
                                                   const float* __restrict__ g1w,
                                                   const float* __restrict__ g1b,
                                                   const float* __restrict__ g2w,
                                                   const float* __restrict__ g2b,
                                                   float* __restrict__ gate_out) {
    __shared__ float qs[DT];
    __shared__ float hx[NHID];
    const int b    = blockIdx.x;
    const int tid  = threadIdx.x;
    const int lane = tid & 31;
    const int wid  = tid >> 5;

    *(float4*)(qs + tid * 4) = *(const float4*)(Q + (size_t)b * DT + tid * 4);
    __syncthreads();

    const float scale = (g_abs[0][b] + g_abs[1][b]) * (1.0f / (float)(C_SZ * DF));

    // warp w computes hidden units 8w .. 8w+7
    #pragma unroll
    for (int j = 0; j < 8; j++) {
        const int h = wid * 8 + j;
        const float* wrow = g1w + (size_t)h * (DT + 1);
        float s = 0.f;
        #pragma unroll
        for (int k = 0; k < 16; k++)
            s = fmaf(qs[lane + 32 * k], wrow[lane + 32 * k], s);
        #pragma unroll
        for (int o = 16; o; o >>= 1) s += __shfl_xor_sync(0xffffffffu, s, o);
        if (lane == 0) hx[h] = s + g1b[h] + scale * wrow[DT];
    }
    __syncthreads();

    if (wid == 0) {
        float h  = hx[lane];
        float ge = 0.5f * h * (1.0f + erff(h * 0.70710678118654752f));
        float y  = g2w[lane] * ge;
        #pragma unroll
        for (int o = 16; o; o >>= 1) y += __shfl_xor_sync(0xffffffffu, y, o);
        if (lane == 0) {
            float gate = 1.0f / (1.0f + expf(-(y + g2b[0])));
            g_gate[b]   = gate;
            gate_out[b] = gate;
        }
    }
}

// ---------------------------------------------------------------------------
// Kernel 3: split-K partial of (acc_total @ Wv^T). Normalization deferred to epi.
// A-load sums the two half-partials on the fly.
// NT GEMM. Tile 32b x 128t, K-half 256, 256 threads, f32x2 inner.
// ---------------------------------------------------------------------------
__global__ __launch_bounds__(256) void out_gemm(const float* __restrict__ Wv) {
    __shared__ float As[2][32 * 36];    // [f][b], stride 36
    __shared__ float Bs[2][32 * 132];   // [f][t], stride 132
    const int tid  = threadIdx.x;
    const int b0   = blockIdx.y * 32;
    const int t0   = blockIdx.x * 128;
    const int kz   = blockIdx.z * (DF / KSPLIT);
    const int wq   = tid >> 5;
    const int lane = tid & 31;
    const int arow = tid >> 3;
    const int kc   = (tid & 7) * 4;

    unsigned long long acc[4][2] = {};

    const size_t aoff = (size_t)(b0 + arow) * DF + kz + kc;
    float4 rA0 = *(const float4*)(g_accP[0] + aoff);
    float4 rA1 = *(const float4*)(g_accP[1] + aoff);
    float4 rB[4];
    #pragma unroll
    for (int p = 0; p < 4; p++)
        rB[p] = *(const float4*)(Wv + (size_t)(t0 + arow + 32 * p) * DF + kz + kc);

    #pragma unroll 1
    for (int it = 0; it < 8; it++) {
        const int cur = it & 1;
        As[cur][(kc + 0) * 36 + arow] = rA0.x + rA1.x;
        As[cur][(kc + 1) * 36 + arow] = rA0.y + rA1.y;
        As[cur][(kc + 2) * 36 + arow] = rA0.z + rA1.z;
        As[cur][(kc + 3) * 36 + arow] = rA0.w + rA1.w;
        #pragma unroll
        for (int p = 0; p < 4; p++) {
            int tr = arow + 32 * p;
            Bs[cur][(kc + 0) * 132 + tr] = rB[p].x;
            Bs[cur][(kc + 1) * 132 + tr] = rB[p].y;
            Bs[cur][(kc + 2) * 132 + tr] = rB[p].z;
            Bs[cur][(kc + 3) * 132 + tr] = rB[p].w;
        }
        if (it < 7) {
            const size_t aoffn = aoff + (size_t)(it + 1) * 32;
            rA0 = *(const float4*)(g_accP[0] + aoffn);
            rA1 = *(const float4*)(g_accP[1] + aoffn);
            const int k0n = kz + (it + 1) * 32;
            #pragma unroll
            for (int p = 0; p < 4; p++)
                rB[p] = *(const float4*)(Wv + (size_t)(t0 + arow + 32 * p) * DF + k0n + kc);
        }
        __syncthreads();
        #pragma unroll
        for (int kk = 0; kk < 32; kk++) {
            float4 a4 = *(const float4*)(&As[cur][kk * 36 + wq * 4]);
            ulonglong2 w = *(const ulonglong2*)(&Bs[cur][kk * 132 + lane * 4]);
            unsigned long long a0 = pack2(a4.x), a1 = pack2(a4.y),
                               a2 = pack2(a4.z), a3 = pack2(a4.w);
            ffma2(acc[0][0], a0, w.x); ffma2(acc[0][1], a0, w.y);
            ffma2(acc[1][0], a1, w.x); ffma2(acc[1][1], a1, w.y);
            ffma2(acc[2][0], a2, w.x); ffma2(acc[2][1], a2, w.y);
            ffma2(acc[3][0], a3, w.x); ffma2(acc[3][1], a3, w.y);
        }
        __syncthreads();
    }

    float* dst = g_outP[blockIdx.z];
    #pragma unroll
    for (int i = 0; i < 4; i++) {
        int bb = b0 + wq * 4 + i;
        float4 v = make_float4(lo32(acc[i][0]), hi32(acc[i][0]),
                               lo32(acc[i][1]), hi32(acc[i][1]));
        *(float4*)(dst + (size_t)bb * DT + t0 + lane * 4) = v;
    }
}

// ---------------------------------------------------------------------------
// Kernel 4: epilogue — out[b][t] = gate[b] * (linv[b]*(p0+p1) + Wv_b[t])
// ---------------------------------------------------------------------------
__global__ __launch_bounds__(256) void out_epi(const float* __restrict__ Wvb,
                                               float* __restrict__ out) {
    int i4 = blockIdx.x * 256 + threadIdx.x;       // float4 index, 131072 total
    int b  = i4 >> 7;
    int t4 = i4 & 127;
    float4 p0 = *(const float4*)(&g_outP[0][i4 * 4]);
    float4 p1 = *(const float4*)(&g_outP[1][i4 * 4]);
    float4 bv = *(const float4*)(Wvb + t4 * 4);
    float linv = 1.0f / (g_lp[0][b] + g_lp[1][b]);
    float g = g_gate[b];
    float4 v;
    v.x = g * (linv * (p0.x + p1.x) + bv.x);
    v.y = g * (linv * (p0.y + p1.y) + bv.y);
    v.z = g * (linv * (p0.z + p1.z) + bv.z);
    v.w = g * (linv * (p0.w + p1.w) + bv.w);
    *(float4*)(out + (size_t)i4 * 4) = v;
}

// ---------------------------------------------------------------------------
// Launch. Inputs: Q, features, Wk_w, Wk_b, Wv_w, Wv_b, g1_w, g1_b, g2_w, g2_b.
// Output: [gate*feat_read (1024x512), gate (1024)].
// Wk_b shifts all scores of a batch equally -> cancels in softmax.
// ---------------------------------------------------------------------------
extern "C" void kernel_launch(void* const* d_in, const int* in_sizes, int n_in,
                              void* d_out, int out_size) {
    const float* Q   = (const float*)d_in[0];
    const float* F   = (const float*)d_in[1];
    const float* Wk  = (const float*)d_in[2];
    const float* Wvw = (const float*)d_in[4];
    const float* Wvb = (const float*)d_in[5];
    const float* g1w = (const float*)d_in[6];
    const float* g1b = (const float*)d_in[7];
    const float* g2w = (const float*)d_in[8];
    const float* g2b = (const float*)d_in[9];
    float* out = (float*)d_out;

    const int attn_smem = (512 + 3 * 16 * DF + 32) * (int)sizeof(float); // ~98.2 KB
    cudaFuncSetAttribute(attn_kernel, cudaFuncAttributeMaxDynamicSharedMemorySize, attn_smem);

    qk_gemm<<<dim3(4, 32, KSPLIT), 256>>>(Q, Wk);
    attn_kernel<<<dim3(B_SZ, 2), 512, attn_smem>>>(F);
    gate_kernel<<<B_SZ, 128>>>(Q, g1w, g1b, g2w, g2b, out + B_SZ * DT);
    out_gemm<<<dim3(4, 32, KSPLIT), 256>>>(Wvw);
    out_epi<<<512, 256>>>(Wvb, out);
}

// round 16
// speedup vs baseline: 1.0311x; 1.0311x over previous
#include <cuda_runtime.h>
#include <math.h>

#define B_SZ 1024
#define C_SZ 256
#define DF   512
#define DT   512
#define NHID 32
#define KSPLIT 2

// Scratch (allocation-free: __device__ globals)
__device__ float g_QkP[KSPLIT][B_SZ * DF];   // split-K partials of Q @ Wk_w
__device__ float g_accP[2][B_SZ * DF];       // per-half UNNORMALIZED weighted feature sums
__device__ float g_lp[2][B_SZ];              // per-half sum of exp weights
__device__ float g_abs[2][B_SZ];             // per-half sum of |f|
__device__ float g_gate[B_SZ];               // sigmoid gate per b
__device__ float g_outP[KSPLIT][B_SZ * DT];  // split-K partials of acc_total @ Wv^T

// ---------------------------------------------------------------------------
// helpers
// ---------------------------------------------------------------------------
__device__ __forceinline__ void cp_async16(float* dst, const float* src) {
    unsigned s = (unsigned)__cvta_generic_to_shared(dst);
    asm volatile("cp.async.cg.shared.global [%0], [%1], 16;\n" :: "r"(s), "l"(src) : "memory");
}
__device__ __forceinline__ unsigned long long pack2(float x) {
    unsigned long long r;
    asm("mov.b64 %0, {%1, %1};" : "=l"(r) : "r"(__float_as_uint(x)));
    return r;
}
__device__ __forceinline__ void ffma2(unsigned long long& acc, unsigned long long a,
                                      unsigned long long w) {
    asm("fma.rn.f32x2 %0, %1, %2, %0;" : "+l"(acc) : "l"(a), "l"(w));
}
__device__ __forceinline__ float lo32(unsigned long long v) {
    return __uint_as_float((unsigned)v);
}
__device__ __forceinline__ float hi32(unsigned long long v) {
    return __uint_as_float((unsigned)(v >> 32));
}

// shared inner product step: 8 b-rows x 4 cols from As/Bs
#define GEMM_INNER(As_, Bs_, BSTRIDE)                                          \
    _Pragma("unroll")                                                          \
    for (int kk = 0; kk < 32; kk++) {                                          \
        float4 alo = *(const float4*)(&(As_)[kk * 36 + wq * 8]);               \
        float4 ahi = *(const float4*)(&(As_)[kk * 36 + wq * 8 + 4]);           \
        ulonglong2 w = *(const ulonglong2*)(&(Bs_)[kk * (BSTRIDE) + lane * 4]);\
        unsigned long long a0 = pack2(alo.x), a1 = pack2(alo.y),               \
                           a2 = pack2(alo.z), a3 = pack2(alo.w);               \
        unsigned long long a4 = pack2(ahi.x), a5 = pack2(ahi.y),               \
                           a6 = pack2(ahi.z), a7 = pack2(ahi.w);               \
        ffma2(acc[0][0], a0, w.x); ffma2(acc[0][1], a0, w.y);                  \
        ffma2(acc[1][0], a1, w.x); ffma2(acc[1][1], a1, w.y);                  \
        ffma2(acc[2][0], a2, w.x); ffma2(acc[2][1], a2, w.y);                  \
        ffma2(acc[3][0], a3, w.x); ffma2(acc[3][1], a3, w.y);                  \
        ffma2(acc[4][0], a4, w.x); ffma2(acc[4][1], a4, w.y);                  \
        ffma2(acc[5][0], a5, w.x); ffma2(acc[5][1], a5, w.y);                  \
        ffma2(acc[6][0], a6, w.x); ffma2(acc[6][1], a6, w.y);                  \
        ffma2(acc[7][0], a7, w.x); ffma2(acc[7][1], a7, w.y);                  \
    }

// ---------------------------------------------------------------------------
// Kernel 1: split-K partial of Qk[b][f] = sum_t Q[b][t] * Wk[t][f]
// Tile 32b x 128f, K-half 256 (8 iters of 32), 128 threads.
// Warp owns 8 b-rows, lane owns 4 f-cols -> 32 outputs/thread, 16 FFMA2/kstep.
// A: LDG + transposed STS (reg-staged). B (k-major): cp.async, no transpose.
// ---------------------------------------------------------------------------
__global__ __launch_bounds__(128) void qk_gemm(const float* __restrict__ Q,
                                               const float* __restrict__ Wk) {
    __shared__ float As[2][32 * 36];   // [k][b], stride 36
    __shared__ float Bs[2][32 * 128];  // [k][f]
    const int tid  = threadIdx.x;
    const int b0   = blockIdx.y * 32;
    const int f0   = blockIdx.x * 128;
    const int kz   = blockIdx.z * (DT / KSPLIT);
    const int wq   = tid >> 5;          // 0..3
    const int lane = tid & 31;
    const int arow = tid >> 3;          // 0..15
    const int kc   = (tid & 7) * 4;
    const int kr   = tid >> 4;          // 0..7
    const int fc   = (tid & 15) * 8;

    unsigned long long acc[8][2] = {};

    float4 rA0 = *(const float4*)(Q + (size_t)(b0 + arow) * DT + kz + kc);
    float4 rA1 = *(const float4*)(Q + (size_t)(b0 + 16 + arow) * DT + kz + kc);
    #pragma unroll
    for (int p = 0; p < 4; p++) {
        int kk = kr + p * 8;
        cp_async16(&Bs[0][kk * 128 + fc],     Wk + (size_t)(kz + kk) * DF + f0 + fc);
        cp_async16(&Bs[0][kk * 128 + fc + 4], Wk + (size_t)(kz + kk) * DF + f0 + fc + 4);
    }
    asm volatile("cp.async.commit_group;\n" ::: "memory");

    #pragma unroll 1
    for (int it = 0; it < 8; it++) {
        const int cur = it & 1, nxt = cur ^ 1;
        As[cur][(kc + 0) * 36 + arow] = rA0.x;
        As[cur][(kc + 1) * 36 + arow] = rA0.y;
        As[cur][(kc + 2) * 36 + arow] = rA0.z;
        As[cur][(kc + 3) * 36 + arow] = rA0.w;
        As[cur][(kc + 0) * 36 + 16 + arow] = rA1.x;
        As[cur][(kc + 1) * 36 + 16 + arow] = rA1.y;
        As[cur][(kc + 2) * 36 + 16 + arow] = rA1.z;
        As[cur][(kc + 3) * 36 + 16 + arow] = rA1.w;
        if (it < 7) {
            const int k0n = kz + (it + 1) * 32;
            rA0 = *(const float4*)(Q + (size_t)(b0 + arow) * DT + k0n + kc);
            rA1 = *(const float4*)(Q + (size_t)(b0 + 16 + arow) * DT + k0n + kc);
            #pragma unroll
            for (int p = 0; p < 4; p++) {
                int kk = kr + p * 8;
                cp_async16(&Bs[nxt][kk * 128 + fc],
                           Wk + (size_t)(k0n + kk) * DF + f0 + fc);
                cp_async16(&Bs[nxt][kk * 128 + fc + 4],
                           Wk + (size_t)(k0n + kk) * DF + f0 + fc + 4);
            }
            asm volatile("cp.async.commit_group;\n" ::: "memory");
            asm volatile("cp.async.wait_group 1;\n" ::: "memory");
        } else {
            asm volatile("cp.async.wait_group 0;\n" ::: "memory");
        }
        __syncthreads();
        GEMM_INNER(As[cur], Bs[cur], 128)
        __syncthreads();
    }
    float* dst = g_QkP[blockIdx.z];
    #pragma unroll
    for (int i = 0; i < 8; i++) {
        float4 v = make_float4(lo32(acc[i][0]), hi32(acc[i][0]),
                               lo32(acc[i][1]), hi32(acc[i][1]));
        *(float4*)(dst + (size_t)(b0 + wq * 8 + i) * DF + f0 + lane * 4) = v;
    }
}

// ---------------------------------------------------------------------------
// Kernel 2: half-batch attention. blockIdx.x = b, blockIdx.y = half (128 ch).
// Register single-read; Qk hoisted; one barrier per chunk; exp w/o max shift.
// Writes UNNORMALIZED partial acc + partial (l, sum|f|).
// ---------------------------------------------------------------------------
__global__ __launch_bounds__(512, 2) void attn_kernel(const float* __restrict__ feat) {
    extern __shared__ float sm[];
    float* Qks = sm;                  // 512 (Qk row, scaled)
    float* buf = sm + 512;            // 3 * 16 * 512 ring (reused for reduction)
    float* aux = buf + 3 * 16 * DF;   // 32: l parts / abs parts

    const int b    = blockIdx.x;
    const int half = blockIdx.y;
    const int tid  = threadIdx.x;
    const int lane = tid & 31;
    const int wid  = tid >> 5;
    const float* Fb = feat + (size_t)b * C_SZ * DF + (size_t)half * 128 * DF;

    const float inv_sqrt_d = 0.044194173824159216f; // 1/sqrt(512)
    Qks[tid] = (g_QkP[0][(size_t)b * DF + tid] + g_QkP[1][(size_t)b * DF + tid]) * inv_sqrt_d;

    #pragma unroll
    for (int s = 0; s < 2; s++) {
        float* dst = buf + s * 16 * DF;
        const float* src = Fb + (size_t)s * 16 * DF;
        #pragma unroll
        for (int i = 0; i < 4; i++)
            cp_async16(dst + 4 * (tid + i * 512), src + 4 * (tid + i * 512));
        asm volatile("cp.async.commit_group;\n" ::: "memory");
    }
    __syncthreads();

    const float4* Qk4 = (const float4*)Qks;
    float4 q[4];
    #pragma unroll
    for (int k = 0; k < 4; k++) q[k] = Qk4[lane + 32 * k];

    float4 acc[4];
    #pragma unroll
    for (int k = 0; k < 4; k++) acc[k] = make_float4(0.f, 0.f, 0.f, 0.f);
    float lpart = 0.f;
    float wabs  = 0.f;

    #pragma unroll 1
    for (int ch = 0; ch < 8; ch++) {
        if (ch < 7) asm volatile("cp.async.wait_group 1;\n" ::: "memory");
        else        asm volatile("cp.async.wait_group 0;\n" ::: "memory");
        __syncthreads();   // sole barrier: chunk ch resident; all warps past ch-1

        if (ch + 2 < 8) {
            float* dst = buf + ((ch + 2) % 3) * 16 * DF;
            const float* src = Fb + (size_t)(ch + 2) * 16 * DF;
            #pragma unroll
            for (int i = 0; i < 4; i++)
                cp_async16(dst + 4 * (tid + i * 512), src + 4 * (tid + i * 512));
            asm volatile("cp.async.commit_group;\n" ::: "memory");
        }

        const float4* row4 = (const float4*)(buf + (ch % 3) * 16 * DF + wid * DF);
        float4 v[4];
        float s = 0.f, a = 0.f;
        #pragma unroll
        for (int k = 0; k < 4; k++) {
            v[k] = row4[lane + 32 * k];
            s = fmaf(q[k].x, v[k].x, s); s = fmaf(q[k].y, v[k].y, s);
            s = fmaf(q[k].z, v[k].z, s); s = fmaf(q[k].w, v[k].w, s);
            a += fabsf(v[k].x) + fabsf(v[k].y) + fabsf(v[k].z) + fabsf(v[k].w);
        }
        #pragma unroll
        for (int o = 16; o; o >>= 1) {
            s += __shfl_xor_sync(0xffffffffu, s, o);
            a += __shfl_xor_sync(0xffffffffu, a, o);
        }
        float p = __expf(s);
        lpart += p;
        wabs  += a;
        #pragma unroll
        for (int k = 0; k < 4; k++) {
            acc[k].x = fmaf(p, v[k].x, acc[k].x);
            acc[k].y = fmaf(p, v[k].y, acc[k].y);
            acc[k].z = fmaf(p, v[k].z, acc[k].z);
            acc[k].w = fmaf(p, v[k].w, acc[k].w);
        }
    }

    __syncthreads();
    float4* red = (float4*)buf;            // [16 warps][128 f4]
    #pragma unroll
    for (int k = 0; k < 4; k++) red[wid * 128 + lane + 32 * k] = acc[k];
    if (lane == 0) { aux[wid] = lpart; aux[16 + wid] = wabs; }
    __syncthreads();

    if (tid < 128) {
        float4 s4 = make_float4(0.f, 0.f, 0.f, 0.f);
        #pragma unroll
        for (int w = 0; w < 16; w++) {
            float4 v = red[w * 128 + tid];
            s4.x += v.x; s4.y += v.y; s4.z += v.z; s4.w += v.w;
        }
        *(float4*)(g_accP[half] + (size_t)b * DF + tid * 4) = s4;
    }
    if (tid == 0) {
        float l = 0.f, t = 0.f;
        #pragma unroll
        for (int w = 0; w < 16; w++) { l += aux[w]; t += aux[16 + w]; }
        g_lp[half][b]  = l;
        g_abs[half][b] = t;
    }
}

// ---------------------------------------------------------------------------
// Kernel 2b: gate MLP. One CTA (128 threads) per b. g1w is L2-hot.
// ---------------------------------------------------------------------------
__global__ __launch_bounds__(128) void gate_kernel(const float* __restrict__ Q,
                                                   const float* __restrict__ g1w,
                                                   const float* __restrict__ g1b,
                                                   const float* __restrict__ g2w,
                                                   const float* __restrict__ g2b,
                                                   float* __restrict__ gate_out) {
    __shared__ float qs[DT];
    __shared__ float hx[NHID];
    const int b    = blockIdx.x;
    const int tid  = threadIdx.x;
    const int lane = tid & 31;
    const int wid  = tid >> 5;

    *(float4*)(qs + tid * 4) = *(const float4*)(Q + (size_t)b * DT + tid * 4);
    __syncthreads();

    const float scale = (g_abs[0][b] + g_abs[1][b]) * (1.0f / (float)(C_SZ * DF));

    #pragma unroll
    for (int j = 0; j < 8; j++) {
        const int h = wid * 8 + j;
        const float* wrow = g1w + (size_t)h * (DT + 1);
        float s = 0.f;
        #pragma unroll
        for (int k = 0; k < 16; k++)
            s = fmaf(qs[lane + 32 * k], wrow[lane + 32 * k], s);
        #pragma unroll
        for (int o = 16; o; o >>= 1) s += __shfl_xor_sync(0xffffffffu, s, o);
        if (lane == 0) hx[h] = s + g1b[h] + scale * wrow[DT];
    }
    __syncthreads();

    if (wid == 0) {
        float h  = hx[lane];
        float ge = 0.5f * h * (1.0f + erff(h * 0.70710678118654752f));
        float y  = g2w[lane] * ge;
        #pragma unroll
        for (int o = 16; o; o >>= 1) y += __shfl_xor_sync(0xffffffffu, y, o);
        if (lane == 0) {
            float gate = 1.0f / (1.0f + expf(-(y + g2b[0])));
            g_gate[b]   = gate;
            gate_out[b] = gate;
        }
    }
}

// ---------------------------------------------------------------------------
// Kernel 3: split-K partial of (acc_total @ Wv^T). Normalization in epi.
// Tile 32b x 128t, K-half 256 (8 iters), 128 threads, 8b x 4t per thread.
// A sums two half-partials on the fly; B: LDG + transposed STS (reg-staged).
// ---------------------------------------------------------------------------
__global__ __launch_bounds__(128) void out_gemm(const float* __restrict__ Wv) {
    __shared__ float As[2][32 * 36];    // [f][b], stride 36
    __shared__ float Bs[2][32 * 132];   // [f][t], stride 132
    const int tid  = threadIdx.x;
    const int b0   = blockIdx.y * 32;
    const int t0   = blockIdx.x * 128;
    const int kz   = blockIdx.z * (DF / KSPLIT);
    const int wq   = tid >> 5;
    const int lane = tid & 31;
    const int arow = tid >> 3;          // 0..15
    const int kc   = (tid & 7) * 4;

    unsigned long long acc[8][2] = {};

    const size_t aoff0 = (size_t)(b0 + arow) * DF + kz + kc;
    const size_t aoff1 = (size_t)(b0 + 16 + arow) * DF + kz + kc;
    float4 rA0a = *(const float4*)(g_accP[0] + aoff0);
    float4 rA0b = *(const float4*)(g_accP[1] + aoff0);
    float4 rA1a = *(const float4*)(g_accP[0] + aoff1);
    float4 rA1b = *(const float4*)(g_accP[1] + aoff1);
    float4 rB[8];
    #pragma unroll
    for (int p = 0; p < 8; p++)
        rB[p] = *(const float4*)(Wv + (size_t)(t0 + arow + 16 * p) * DF + kz + kc);

    #pragma unroll 1
    for (int it = 0; it < 8; it++) {
        const int cur = it & 1;
        As[cur][(kc + 0) * 36 + arow] = rA0a.x + rA0b.x;
        As[cur][(kc + 1) * 36 + arow] = rA0a.y + rA0b.y;
        As[cur][(kc + 2) * 36 + arow] = rA0a.z + rA0b.z;
        As[cur][(kc + 3) * 36 + arow] = rA0a.w + rA0b.w;
        As[cur][(kc + 0) * 36 + 16 + arow] = rA1a.x + rA1b.x;
        As[cur][(kc + 1) * 36 + 16 + arow] = rA1a.y + rA1b.y;
        As[cur][(kc + 2) * 36 + 16 + arow] = rA1a.z + rA1b.z;
        As[cur][(kc + 3) * 36 + 16 + arow] = rA1a.w + rA1b.w;
        #pragma unroll
        for (int p = 0; p < 8; p++) {
            int tr = arow + 16 * p;
            Bs[cur][(kc + 0) * 132 + tr] = rB[p].x;
            Bs[cur][(kc + 1) * 132 + tr] = rB[p].y;
            Bs[cur][(kc + 2) * 132 + tr] = rB[p].z;
            Bs[cur][(kc + 3) * 132 + tr] = rB[p].w;
        }
        if (it < 7) {
            const int koff = (it + 1) * 32;
            rA0a = *(const float4*)(g_accP[0] + aoff0 + koff);
            rA0b = *(const float4*)(g_accP[1] + aoff0 + koff);
            rA1a = *(const float4*)(g_accP[0] + aoff1 + koff);
            rA1b = *(const float4*)(g_accP[1] + aoff1 + koff);
            const int k0n = kz + koff;
            #pragma unroll
            for (int p = 0; p < 8; p++)
                rB[p] = *(const float4*)(Wv + (size_t)(t0 + arow + 16 * p) * DF + k0n + kc);
        }
        __syncthreads();
        GEMM_INNER(As[cur], Bs[cur], 132)
        __syncthreads();
    }

    float* dst = g_outP[blockIdx.z];
    #pragma unroll
    for (int i = 0; i < 8; i++) {
        int bb = b0 + wq * 8 + i;
        float4 v = make_float4(lo32(acc[i][0]), hi32(acc[i][0]),
                               lo32(acc[i][1]), hi32(acc[i][1]));
        *(float4*)(dst + (size_t)bb * DT + t0 + lane * 4) = v;
    }
}

// ---------------------------------------------------------------------------
// Kernel 4: epilogue — out[b][t] = gate[b] * (linv[b]*(p0+p1) + Wv_b[t])
// 4 float4 per thread (8 LDGs in flight) to cover LDG latency.
// ---------------------------------------------------------------------------
__global__ __launch_bounds__(256) void out_epi(const float* __restrict__ Wvb,
                                               float* __restrict__ out) {
    int base = (blockIdx.x * 256 + threadIdx.x) * 4;   // float4 index; 131072 total
    int b  = base >> 7;                                // 4 consecutive f4 share b
    int t4 = base & 127;
    float4 p0[4], p1[4];
    #pragma unroll
    for (int j = 0; j < 4; j++) {
        p0[j] = *(const float4*)(&g_outP[0][(base + j) * 4]);
        p1[j] = *(const float4*)(&g_outP[1][(base + j) * 4]);
    }
    float linv = 1.0f / (g_lp[0][b] + g_lp[1][b]);
    float g = g_gate[b];
    #pragma unroll
    for (int j = 0; j < 4; j++) {
        float4 bv = *(const float4*)(Wvb + (t4 + j) * 4);
        float4 v;
        v.x = g * (linv * (p0[j].x + p1[j].x) + bv.x);
        v.y = g * (linv * (p0[j].y + p1[j].y) + bv.y);
        v.z = g * (linv * (p0[j].z + p1[j].z) + bv.z);
        v.w = g * (linv * (p0[j].w + p1[j].w) + bv.w);
        *(float4*)(out + (size_t)(base + j) * 4) = v;
    }
}

// ---------------------------------------------------------------------------
// Launch. Inputs: Q, features, Wk_w, Wk_b, Wv_w, Wv_b, g1_w, g1_b, g2_w, g2_b.
// Output: [gate*feat_read (1024x512), gate (1024)].
// Wk_b shifts all scores of a batch equally -> cancels in softmax.
// ---------------------------------------------------------------------------
extern "C" void kernel_launch(void* const* d_in, const int* in_sizes, int n_in,
                              void* d_out, int out_size) {
    const float* Q   = (const float*)d_in[0];
    const float* F   = (const float*)d_in[1];
    const float* Wk  = (const float*)d_in[2];
    const float* Wvw = (const float*)d_in[4];
    const float* Wvb = (const float*)d_in[5];
    const float* g1w = (const float*)d_in[6];
    const float* g1b = (const float*)d_in[7];
    const float* g2w = (const float*)d_in[8];
    const float* g2b = (const float*)d_in[9];
    float* out = (float*)d_out;

    const int attn_smem = (512 + 3 * 16 * DF + 32) * (int)sizeof(float); // ~98.2 KB
    cudaFuncSetAttribute(attn_kernel, cudaFuncAttributeMaxDynamicSharedMemorySize, attn_smem);

    qk_gemm<<<dim3(4, 32, KSPLIT), 128>>>(Q, Wk);
    attn_kernel<<<dim3(B_SZ, 2), 512, attn_smem>>>(F);
    gate_kernel<<<B_SZ, 128>>>(Q, g1w, g1b, g2w, g2b, out + B_SZ * DT);
    out_gemm<<<dim3(4, 32, KSPLIT), 128>>>(Wvw);
    out_epi<<<128, 256>>>(Wvb, out);
}